// round 7
// baseline (speedup 1.0000x reference)
#include <cuda_runtime.h>

// Problem dims
#define DM     1792           // D_MODEL
#define BBDIM  256            // BB
#define I_DIM  2048           // inner dim I
#define G_DIM  8192           // 4*I

// Scratch state (allocation-free rule: __device__ globals)
__device__ float g_z[6 * G_DIM];      // gate preactivations (Wih part + both biases)
__device__ float g_h[2][I_DIM];       // ping-pong hidden state
__device__ float g_c[2][I_DIM];       // ping-pong cell state

__device__ __forceinline__ float sigmoidf_(float x) {
    return 1.0f / (1.0f + expf(-x));
}

__device__ __forceinline__ float dot4(float4 a, float4 b) {
    return a.x * b.x + a.y * b.y + a.z * b.z + a.w * b.w;
}

// ---------------------------------------------------------------------------
// Quad-row warp dot: one warp streams FOUR weight rows against one smem
// vector with distance-2 prefetch (1 float4 per row per stage -> 8-12
// LDG.128 continuously in flight). The h chunk is loaded from smem ONCE per
// stage and reused by all 4 rows. Fully unrolled (compile-time k), so the
// prefetch guard is resolved statically.
// ---------------------------------------------------------------------------
template <int NITER>
__device__ __forceinline__ void quad_dot(const float4* __restrict__ r0,
                                         const float4* __restrict__ r1,
                                         const float4* __restrict__ r2,
                                         const float4* __restrict__ r3,
                                         const float4* __restrict__ v4,
                                         int lane, float acc[4])
{
    float4 a0 = __ldcs(r0 + lane),      a1 = __ldcs(r1 + lane),
           a2 = __ldcs(r2 + lane),      a3 = __ldcs(r3 + lane);
    float4 b0 = __ldcs(r0 + lane + 32), b1 = __ldcs(r1 + lane + 32),
           b2 = __ldcs(r2 + lane + 32), b3 = __ldcs(r3 + lane + 32);

    acc[0] = acc[1] = acc[2] = acc[3] = 0.f;

#pragma unroll
    for (int k = 0; k < NITER; ++k) {
        float4 n0, n1, n2, n3;
        if (k + 2 < NITER) {
            n0 = __ldcs(r0 + lane + (k + 2) * 32);
            n1 = __ldcs(r1 + lane + (k + 2) * 32);
            n2 = __ldcs(r2 + lane + (k + 2) * 32);
            n3 = __ldcs(r3 + lane + (k + 2) * 32);
        }
        float4 h = v4[lane + k * 32];
        acc[0] += dot4(a0, h);
        acc[1] += dot4(a1, h);
        acc[2] += dot4(a2, h);
        acc[3] += dot4(a3, h);
        if (k + 1 < NITER) { a0 = b0; a1 = b1; a2 = b2; a3 = b3; }
        if (k + 2 < NITER) { b0 = n0; b1 = n1; b2 = n2; b3 = n3; }
    }
}

// Four interleaved butterfly reductions (pipelined SHFLs, ~1 chain of 5).
__device__ __forceinline__ void warp_sum4(float acc[4]) {
#pragma unroll
    for (int o = 16; o > 0; o >>= 1) {
        acc[0] += __shfl_xor_sync(0xffffffffu, acc[0], o);
        acc[1] += __shfl_xor_sync(0xffffffffu, acc[1], o);
        acc[2] += __shfl_xor_sync(0xffffffffu, acc[2], o);
        acc[3] += __shfl_xor_sync(0xffffffffu, acc[3], o);
    }
}

#define GS4 ((size_t)I_DIM * I_DIM / 4)   // gate stride in float4 (8192*2048 matrix)

// ---------------------------------------------------------------------------
// K0: z for cells 0 and 1. 1024 blocks x 128: block b < 512 -> cell 0.
// Warp handles 4 consecutive rows (quad). 512 blocks * 4 warps = 2048 quads
// = 8192 rows per cell.
// ---------------------------------------------------------------------------
__global__ void __launch_bounds__(128, 7) precompute_z01(
    const float* __restrict__ x,     // (6, 1792)
    const float* __restrict__ y,     // (5, 256)
    const float* __restrict__ Wih5,  // (5, 8192, 2048)
    const float* __restrict__ bih5,  // (5, 8192)
    const float* __restrict__ bhh5)  // (5, 8192)
{
    __shared__ float xs[I_DIM];

    const int t   = blockIdx.x >> 9;               // cell 0 or 1
    const int qb  = blockIdx.x & 511;
    const int tid = threadIdx.x;
    const int w    = tid >> 5;
    const int lane = tid & 31;

    for (int k = tid; k < DM; k += 128)    xs[k]      = x[t * DM + k];
    for (int k = tid; k < BBDIM; k += 128) xs[DM + k] = y[t * BBDIM + k];
    __syncthreads();

    const int r = ((qb << 2) + w) << 2;            // first row of the quad
    const float4* r0 = (const float4*)(Wih5 + ((size_t)t * G_DIM + r) * I_DIM);
    const float4* r1 = r0 + (I_DIM / 4);
    const float4* r2 = r0 + 2 * (I_DIM / 4);
    const float4* r3 = r0 + 3 * (I_DIM / 4);

    float acc[4];
    quad_dot<16>(r0, r1, r2, r3, (const float4*)xs, lane, acc);
    warp_sum4(acc);

    if (lane == 0) {
        const size_t zb = (size_t)t * G_DIM + r;
#pragma unroll
        for (int u = 0; u < 4; ++u)
            g_z[zb + u] = acc[u] + bih5[zb + u] + bhh5[zb + u];
    }
}

// ---------------------------------------------------------------------------
// step 0: h0 = c0 = 0 -> Whh contributes nothing, f*c0 = 0. (skips Whh5[0])
// ---------------------------------------------------------------------------
__global__ void step0_kernel() {
    int j = blockIdx.x * blockDim.x + threadIdx.x;
    if (j >= I_DIM) return;
    float zi = g_z[j];
    float zg = g_z[2 * I_DIM + j];
    float zo = g_z[3 * I_DIM + j];
    float c  = sigmoidf_(zi) * tanhf(zg);
    float h  = sigmoidf_(zo) * tanhf(c);
    g_c[0][j] = c;
    g_h[0][j] = h;
}

// ---------------------------------------------------------------------------
// Fused kernel. Blocks [0,512): recurrent step t — each warp owns ONE j and
// computes all 4 gate rows of Whh, then does the full gate epilogue in
// lane 0 (no cross-warp coupling). Blocks [512,...): z-precompute for the
// next cell, 4 consecutive Wih rows per warp.
//
// mode 0: z = full cell t+1 (8192 rows, 512 z-blocks, K=2048)
// mode 1: z = final-cell slice (rows g*2048+[1792,2048) of WihF, 1024 rows,
//         64 z-blocks, K=1792) — only h[-256:] of the final cell is needed.
// ---------------------------------------------------------------------------
#define RECB 512

__global__ void __launch_bounds__(128, 7) fused_step(
    const float* __restrict__ whh,   // (8192, 2048) Whh for step t
    int zoff, int pin, int pout,
    const float* __restrict__ wz,    // Wih for next cell
    const float* __restrict__ xvec,  // x row for next cell
    const float* __restrict__ yvec,  // y row for next cell (null in mode 1)
    const float* __restrict__ bih,   // bih for next cell
    const float* __restrict__ bhh,   // bhh for next cell
    int zout, int mode)
{
    __shared__ float sbuf[I_DIM];

    const int tid  = threadIdx.x;
    const int w    = tid >> 5;
    const int lane = tid & 31;

    if (blockIdx.x < RECB) {
        // ---------------- recurrent role: 1 warp = 1 j, 4 gate rows -------
        {
            const float4* gh4 = (const float4*)g_h[pin];
            float4* s4 = (float4*)sbuf;
#pragma unroll
            for (int k = 0; k < 4; ++k) s4[tid + k * 128] = gh4[tid + k * 128];
        }
        __syncthreads();

        const int j = (blockIdx.x << 2) + w;
        const float4* r0 = (const float4*)(whh + (size_t)j * I_DIM);
        const float4* r1 = r0 + GS4;
        const float4* r2 = r0 + 2 * GS4;
        const float4* r3 = r0 + 3 * GS4;

        float acc[4];
        quad_dot<16>(r0, r1, r2, r3, (const float4*)sbuf, lane, acc);
        warp_sum4(acc);

        if (lane == 0) {
            const float* z = g_z + zoff;
            float gi = z[j]             + acc[0];
            float gf = z[I_DIM + j]     + acc[1];
            float gg = z[2 * I_DIM + j] + acc[2];
            float go = z[3 * I_DIM + j] + acc[3];
            float c  = sigmoidf_(gf) * g_c[pin][j] + sigmoidf_(gi) * tanhf(gg);
            float h  = sigmoidf_(go) * tanhf(c);
            g_c[pout][j] = c;
            g_h[pout][j] = h;
        }
    } else {
        // ---------------- z-precompute role ------------------------------
        const int q = ((blockIdx.x - RECB) << 2) + w;   // quad index

        if (mode == 0) {
            for (int k = tid; k < DM; k += 128)    sbuf[k]      = xvec[k];
            for (int k = tid; k < BBDIM; k += 128) sbuf[DM + k] = yvec[k];
            __syncthreads();

            const int r = q << 2;
            const float4* r0 = (const float4*)(wz + (size_t)r * I_DIM);
            const float4* r1 = r0 + (I_DIM / 4);
            const float4* r2 = r0 + 2 * (I_DIM / 4);
            const float4* r3 = r0 + 3 * (I_DIM / 4);

            float acc[4];
            quad_dot<16>(r0, r1, r2, r3, (const float4*)sbuf, lane, acc);
            warp_sum4(acc);

            if (lane == 0) {
#pragma unroll
                for (int u = 0; u < 4; ++u)
                    g_z[zout + r + u] = acc[u] + bih[r + u] + bhh[r + u];
            }
        } else {
            for (int k = tid; k < DM; k += 128) sbuf[k] = xvec[k];
            __syncthreads();

            const int rl = q << 2;                  // 0..1020, step 4
            const int g  = rl >> 8;
            const int jj = rl & 255;
            const int r  = g * I_DIM + DM + jj;     // 4 consecutive real rows
            const float4* r0 = (const float4*)(wz + (size_t)r * DM);
            const float4* r1 = r0 + (DM / 4);
            const float4* r2 = r0 + 2 * (DM / 4);
            const float4* r3 = r0 + 3 * (DM / 4);

            float acc[4];
            quad_dot<14>(r0, r1, r2, r3, (const float4*)sbuf, lane, acc);
            warp_sum4(acc);

            if (lane == 0) {
#pragma unroll
                for (int u = 0; u < 4; ++u)
                    g_z[zout + r + u] = acc[u] + bih[r + u] + bhh[r + u];
            }
        }
    }
}

// ---------------------------------------------------------------------------
// Final step: only j in [1792, 2048). 64 blocks x 128; warp owns one j,
// all 4 gate rows of WhhF. Writes d_out directly.
// ---------------------------------------------------------------------------
__global__ void __launch_bounds__(128, 7) final_step(
    const float* __restrict__ whhF,  // (8192, 2048)
    int pin,
    float* __restrict__ out)
{
    __shared__ float hs[I_DIM];

    const int tid  = threadIdx.x;
    const int w    = tid >> 5;
    const int lane = tid & 31;

    {
        const float4* gh4 = (const float4*)g_h[pin];
        float4* s4 = (float4*)hs;
#pragma unroll
        for (int k = 0; k < 4; ++k) s4[tid + k * 128] = gh4[tid + k * 128];
    }
    __syncthreads();

    const int j = DM + (blockIdx.x << 2) + w;      // 1792 .. 2047
    const float4* r0 = (const float4*)(whhF + (size_t)j * I_DIM);
    const float4* r1 = r0 + GS4;
    const float4* r2 = r0 + 2 * GS4;
    const float4* r3 = r0 + 3 * GS4;

    float acc[4];
    quad_dot<16>(r0, r1, r2, r3, (const float4*)hs, lane, acc);
    warp_sum4(acc);

    if (lane == 0) {
        const float* z = g_z + 5 * G_DIM;
        float gi = z[j]             + acc[0];
        float gf = z[I_DIM + j]     + acc[1];
        float gg = z[2 * I_DIM + j] + acc[2];
        float go = z[3 * I_DIM + j] + acc[3];
        float c  = sigmoidf_(gf) * g_c[pin][j] + sigmoidf_(gi) * tanhf(gg);
        float h  = sigmoidf_(go) * tanhf(c);
        out[j - DM] = h;
    }
}

// ---------------------------------------------------------------------------
extern "C" void kernel_launch(void* const* d_in, const int* in_sizes, int n_in,
                              void* d_out, int out_size)
{
    const float* x    = (const float*)d_in[0];
    const float* y    = (const float*)d_in[1];
    const float* Wih5 = (const float*)d_in[2];
    const float* Whh5 = (const float*)d_in[3];
    const float* bih5 = (const float*)d_in[4];
    const float* bhh5 = (const float*)d_in[5];
    const float* WihF = (const float*)d_in[6];
    const float* WhhF = (const float*)d_in[7];
    const float* bihF = (const float*)d_in[8];
    const float* bhhF = (const float*)d_in[9];
    float* out = (float*)d_out;

    (void)in_sizes; (void)n_in; (void)out_size;

    const size_t WSTEP = (size_t)G_DIM * I_DIM;    // elems per (8192,2048) matrix

    // K0: z[0] and z[1] (134 MB, fully parallel, one wave)
    precompute_z01<<<1024, 128>>>(x, y, Wih5, bih5, bhh5);

    // step 0 (h0=c0=0: no Whh read)
    step0_kernel<<<(I_DIM + 255) / 256, 256>>>();

    // S1..S3: step t fused with z-precompute for cell t+1 (134 MB each)
    int pin = 0;
    for (int t = 1; t <= 3; ++t) {
        fused_step<<<RECB + 512, 128>>>(
            Whh5 + (size_t)t * WSTEP, t * G_DIM, pin, 1 - pin,
            Wih5 + (size_t)(t + 1) * WSTEP,
            x + (t + 1) * DM, y + (t + 1) * BBDIM,
            bih5 + (size_t)(t + 1) * G_DIM, bhh5 + (size_t)(t + 1) * G_DIM,
            (t + 1) * G_DIM, /*mode=*/0);
        pin = 1 - pin;
    }

    // S4: step 4 fused with the FINAL-cell z slice (67 + 7.3 MB)
    fused_step<<<RECB + 64, 128>>>(
        Whh5 + (size_t)4 * WSTEP, 4 * G_DIM, pin, 1 - pin,
        WihF, x + 5 * DM, nullptr,
        bihF, bhhF, 5 * G_DIM, /*mode=*/1);
    pin = 1 - pin;

    // S5: final step, sliced to the 256 needed outputs (8.4 MB)
    final_step<<<64, 128>>>(WhhF, pin, out);
}